// round 8
// baseline (speedup 1.0000x reference)
#include <cuda_runtime.h>
#include <cstdint>

#define SIZE_SETS 50000
#define NS 32
#define OUTP 64
#define MID 8
#define NROWS (SIZE_SETS * NS)
#define WPB 2                      // warps per block
#define BN_BLOCKS 592

// ---------------- device scratch (no allocation allowed) ----------------
__device__ __align__(128) float  g_acc[SIZE_SETS * 16]; // [s][0..7]=gsum, [8..15]=numer
__device__ float  g_bnp[BN_BLOCKS][5];                  // per-block moment partials
__device__ float  g_consts[32];                         // [0..3]=A, [4..5]=shift, [6..13]=C0, [14..21]=C1, [22..29]=D

// ---------------- helpers ----------------
__device__ __forceinline__ void ffma2(unsigned long long& d, unsigned long long a, unsigned long long b) {
    asm("fma.rn.f32x2 %0, %1, %2, %0;" : "+l"(d) : "l"(a), "l"(b));
}
__device__ __forceinline__ void fadd2(unsigned long long& d, unsigned long long a) {
    asm("add.rn.f32x2 %0, %1, %0;" : "+l"(d) : "l"(a));
}
__device__ __forceinline__ float2 unpk(unsigned long long v) {
    float2 r; asm("mov.b64 {%0, %1}, %2;" : "=f"(r.x), "=f"(r.y) : "l"(v)); return r;
}
__device__ __forceinline__ unsigned long long pk(float x, float y) {
    unsigned long long r; asm("mov.b64 %0, {%1, %2};" : "=l"(r) : "f"(x), "f"(y)); return r;
}
__device__ __forceinline__ void red4(float* p, float a, float b, float c, float d) {
    asm volatile("red.global.add.v4.f32 [%0], {%1, %2, %3, %4};"
                 :: "l"(p), "f"(a), "f"(b), "f"(c), "f"(d) : "memory");
}

// ---------------- kernel 1: zero g_acc + per-block raw moments of translation ----------------
__global__ void k_bn(const float* __restrict__ tr) {
    // zero the scatter accumulator (grid-stride)
    for (int k = blockIdx.x * blockDim.x + threadIdx.x; k < SIZE_SETS * 16;
         k += gridDim.x * blockDim.x) g_acc[k] = 0.f;

    float s0 = 0.f, s1 = 0.f, q00 = 0.f, q01 = 0.f, q11 = 0.f;
    const float2* t2 = (const float2*)tr;
    for (int i = blockIdx.x * blockDim.x + threadIdx.x; i < NROWS; i += gridDim.x * blockDim.x) {
        float2 t = t2[i];
        s0 += t.x; s1 += t.y;
        q00 += t.x * t.x; q01 += t.x * t.y; q11 += t.y * t.y;
    }
    #pragma unroll
    for (int o = 16; o; o >>= 1) {
        s0  += __shfl_down_sync(0xffffffffu, s0, o);
        s1  += __shfl_down_sync(0xffffffffu, s1, o);
        q00 += __shfl_down_sync(0xffffffffu, q00, o);
        q01 += __shfl_down_sync(0xffffffffu, q01, o);
        q11 += __shfl_down_sync(0xffffffffu, q11, o);
    }
    __shared__ float sh[5][8];
    int w = threadIdx.x >> 5, l = threadIdx.x & 31;
    if (l == 0) { sh[0][w] = s0; sh[1][w] = s1; sh[2][w] = q00; sh[3][w] = q01; sh[4][w] = q11; }
    __syncthreads();
    if (threadIdx.x < 5) {
        float t = 0.f;
        #pragma unroll
        for (int k = 0; k < 8; k++) t += sh[threadIdx.x][k];
        g_bnp[blockIdx.x][threadIdx.x] = t;
    }
}

// ---------------- kernel 2: reduce moments, fold BN + positional constants ----------------
__global__ void k_setup(const float* __restrict__ Wq, const float* __restrict__ bq,
                        const float* __restrict__ Wp1, const float* __restrict__ gamma,
                        const float* __restrict__ beta, const float* __restrict__ Wp2,
                        const float* __restrict__ bp2) {
    __shared__ double bn[5];
    int t = threadIdx.x;
    if (t < 5) {
        double acc = 0.0;
        for (int i = 0; i < BN_BLOCKS; i++) acc += (double)g_bnp[i][t];
        bn[t] = acc;
    }
    __syncthreads();
    if (t < 2) {
        double Nf = (double)NROWS;
        double w0 = (double)Wp1[t * 2 + 0], w1 = (double)Wp1[t * 2 + 1];
        double Tsum = w0 * bn[0] + w1 * bn[1];
        double Tsq  = w0 * w0 * bn[2] + 2.0 * w0 * w1 * bn[3] + w1 * w1 * bn[4];
        double mean = Tsum / Nf;
        double var  = Tsq / Nf - mean * mean;
        double scale = (double)gamma[t] / sqrt(var + 1e-5);
        double shift = (double)beta[t] - mean * scale;
        g_consts[t * 2 + 0] = (float)(w0 * scale);
        g_consts[t * 2 + 1] = (float)(w1 * scale);
        g_consts[4 + t]     = (float)shift;
    }
    if (t < 8) {
        float c0 = 0.f, c1 = 0.f, d = 0.f;
        for (int k = 0; k < OUTP; k++) {
            float wq = Wq[t * OUTP + k];
            c0 += Wp2[k * 2 + 0] * wq;
            c1 += Wp2[k * 2 + 1] * wq;
            d  += bp2[k] * wq;
        }
        g_consts[6 + t]  = c0;
        g_consts[14 + t] = c1;
        g_consts[22 + t] = d + bq[t];
    }
}

// ---------------- kernel 3: fused main — warp = 2 sets, no block syncs ----------------
__global__ void __launch_bounds__(64, 5)
k_main(const float* __restrict__ outputs, const float* __restrict__ translation,
       const int* __restrict__ indexes, const float* __restrict__ Wq,
       const float* __restrict__ Wv, const float* __restrict__ bv_,
       float* __restrict__ out) {
    __shared__ __align__(16) float sh_x[WPB * 2][32 * 68]; // per-warp 2-set staging
    __shared__ __align__(16) float sh_w[2][8 * 64];        // [0]=Wq, [1]=Wv (broadcast)
    __shared__ float sh_c[32];
    __shared__ float sh_bv[8];

    int tid = threadIdx.x;
    for (int i = tid; i < 512; i += 64) { sh_w[0][i] = Wq[i]; sh_w[1][i] = Wv[i]; }
    if (tid < 32) sh_c[tid] = g_consts[tid];
    if (tid < 8)  sh_bv[tid] = bv_[tid];
    __syncthreads();

    const float A00 = sh_c[0], A01 = sh_c[1], A10 = sh_c[2], A11 = sh_c[3];
    const float SH0 = sh_c[4], SH1 = sh_c[5];

    int warp = tid >> 5, lane = tid & 31;
    int c4 = lane & 15, rhalf = lane >> 4;                 // loader mapping
    float* myx0 = &sh_x[warp * 2 + 0][0];
    float* myx1 = &sh_x[warp * 2 + 1][0];

    const ulonglong2* wq = (const ulonglong2*)&sh_w[0][0];
    const ulonglong2* wv = (const ulonglong2*)&sh_w[1][0];
    const ulonglong2* xr0 = (const ulonglong2*)&myx0[lane * 68];
    const ulonglong2* xr1 = (const ulonglong2*)&myx1[lane * 68];

    const int stride = gridDim.x * WPB * 2;
    for (int s0 = (blockIdx.x * WPB + warp) * 2; s0 < SIZE_SETS; s0 += stride) {
        int s1 = s0 + 1;
        // --- per-row metadata (coalesced, overlaps with staging) ---
        float2 t2v0 = ((const float2*)translation)[s0 * NS + lane];
        float2 t2v1 = ((const float2*)translation)[s1 * NS + lane];
        int idx0 = indexes[s0 * NS + lane];
        int idx1 = indexes[s1 * NS + lane];

        // --- stage both sets (32 coalesced LDG.128 in flight) + feature sums ---
        const float4* src0 = (const float4*)(outputs + (size_t)s0 * (NS * OUTP));
        const float4* src1 = (const float4*)(outputs + (size_t)s1 * (NS * OUTP));
        unsigned long long f0lo = 0ull, f0hi = 0ull, f1lo = 0ull, f1hi = 0ull;
        #pragma unroll
        for (int t = 0; t < 16; t++) {
            float4 v0 = src0[lane + 32 * t];
            float4 v1 = src1[lane + 32 * t];
            fadd2(f0lo, pk(v0.x, v0.y)); fadd2(f0hi, pk(v0.z, v0.w));
            fadd2(f1lo, pk(v1.x, v1.y)); fadd2(f1hi, pk(v1.z, v1.w));
            *(float4*)&myx0[(rhalf + 2 * t) * 68 + c4 * 4] = v0;
            *(float4*)&myx1[(rhalf + 2 * t) * 68 + c4 * 4] = v1;
        }
        fadd2(f0lo, __shfl_xor_sync(0xffffffffu, f0lo, 16));
        fadd2(f0hi, __shfl_xor_sync(0xffffffffu, f0hi, 16));
        fadd2(f1lo, __shfl_xor_sync(0xffffffffu, f1lo, 16));
        fadd2(f1hi, __shfl_xor_sync(0xffffffffu, f1hi, 16));
        {
            float2 alo = unpk(f0lo), ahi = unpk(f0hi);
            float2 blo = unpk(f1lo), bhi = unpk(f1hi);
            if (lane < 16)
                *(float4*)&out[(size_t)s0 * OUTP + lane * 4] = make_float4(alo.x, alo.y, ahi.x, ahi.y);
            else
                *(float4*)&out[(size_t)s1 * OUTP + (lane - 16) * 4] = make_float4(blo.x, blo.y, bhi.x, bhi.y);
        }
        __syncwarp();

        // --- q/v dots for both sets: lane = row, weights broadcast once per pair ---
        unsigned long long q0[8], v0a[8], q1[8], v1a[8];
        #pragma unroll
        for (int j = 0; j < 8; j++) { q0[j] = v0a[j] = q1[j] = v1a[j] = 0ull; }

        #pragma unroll 2
        for (int k4 = 0; k4 < 16; k4++) {
            ulonglong2 x0 = xr0[k4];
            ulonglong2 x1 = xr1[k4];
            #pragma unroll
            for (int j = 0; j < 8; j++) {
                ulonglong2 a = wq[j * 16 + k4];
                ulonglong2 b = wv[j * 16 + k4];
                ffma2(q0[j], x0.x, a.x); ffma2(q0[j], x0.y, a.y);
                ffma2(q1[j], x1.x, a.x); ffma2(q1[j], x1.y, a.y);
                ffma2(v0a[j], x0.x, b.x); ffma2(v0a[j], x0.y, b.y);
                ffma2(v1a[j], x1.x, b.x); ffma2(v1a[j], x1.y, b.y);
            }
        }
        __syncwarp();   // all lanes done reading staging before next iteration

        // --- epilogue set 0 ---
        {
            float a0 = fmaxf(fmaf(A00, t2v0.x, fmaf(A01, t2v0.y, SH0)), 0.f);
            float a1 = fmaxf(fmaf(A10, t2v0.x, fmaf(A11, t2v0.y, SH1)), 0.f);
            float e8[8], ve8[8];
            #pragma unroll
            for (int j = 0; j < 8; j++) {
                float2 qq = unpk(q0[j]);
                float qs = qq.x + qq.y + fmaf(a0, sh_c[6 + j], fmaf(a1, sh_c[14 + j], sh_c[22 + j]));
                float2 vv = unpk(v0a[j]);
                float vs = vv.x + vv.y + sh_bv[j];
                float e = __expf(qs);
                e8[j] = e; ve8[j] = vs * e;
            }
            float* dst = &g_acc[(size_t)idx0 * 16];
            red4(dst + 0,  e8[0],  e8[1],  e8[2],  e8[3]);
            red4(dst + 4,  e8[4],  e8[5],  e8[6],  e8[7]);
            red4(dst + 8,  ve8[0], ve8[1], ve8[2], ve8[3]);
            red4(dst + 12, ve8[4], ve8[5], ve8[6], ve8[7]);
        }
        // --- epilogue set 1 ---
        {
            float a0 = fmaxf(fmaf(A00, t2v1.x, fmaf(A01, t2v1.y, SH0)), 0.f);
            float a1 = fmaxf(fmaf(A10, t2v1.x, fmaf(A11, t2v1.y, SH1)), 0.f);
            float e8[8], ve8[8];
            #pragma unroll
            for (int j = 0; j < 8; j++) {
                float2 qq = unpk(q1[j]);
                float qs = qq.x + qq.y + fmaf(a0, sh_c[6 + j], fmaf(a1, sh_c[14 + j], sh_c[22 + j]));
                float2 vv = unpk(v1a[j]);
                float vs = vv.x + vv.y + sh_bv[j];
                float e = __expf(qs);
                e8[j] = e; ve8[j] = vs * e;
            }
            float* dst = &g_acc[(size_t)idx1 * 16];
            red4(dst + 0,  e8[0],  e8[1],  e8[2],  e8[3]);
            red4(dst + 4,  e8[4],  e8[5],  e8[6],  e8[7]);
            red4(dst + 8,  ve8[0], ve8[1], ve8[2], ve8[3]);
            red4(dst + 12, ve8[4], ve8[5], ve8[6], ve8[7]);
        }
    }
}

// ---------------- kernel 4: finalize out += tiled(numer/gsum) ----------------
__global__ void k_fin(float* __restrict__ out) {
    int i = blockIdx.x * blockDim.x + threadIdx.x;
    if (i < SIZE_SETS * OUTP) {
        int s = i >> 6, j = i & 7;
        float g = g_acc[s * 16 + j];
        float n = g_acc[s * 16 + 8 + j];
        out[i] += (g > 0.f) ? (n / g) : 0.f;
    }
}

// ---------------- launch ----------------
extern "C" void kernel_launch(void* const* d_in, const int* in_sizes, int n_in,
                              void* d_out, int out_size) {
    const float* outputs     = (const float*)d_in[0];
    const float* translation = (const float*)d_in[1];
    const int*   indexes     = (const int*)d_in[2];
    const float* W_q   = (const float*)d_in[3];
    const float* b_q   = (const float*)d_in[4];
    const float* W_v   = (const float*)d_in[5];
    const float* b_v   = (const float*)d_in[6];
    const float* W_p1  = (const float*)d_in[7];
    const float* gamma = (const float*)d_in[8];
    const float* beta  = (const float*)d_in[9];
    const float* W_p2  = (const float*)d_in[10];
    const float* b_p2  = (const float*)d_in[11];
    float* out = (float*)d_out;

    k_bn<<<BN_BLOCKS, 256>>>(translation);
    k_setup<<<1, 64>>>(W_q, b_q, W_p1, gamma, beta, W_p2, b_p2);
    k_main<<<2500, 64>>>(outputs, translation, indexes, W_q, W_v, b_v, out);
    k_fin<<<(SIZE_SETS * OUTP + 255) / 256, 256>>>(out);
}

// round 11
// speedup vs baseline: 1.0578x; 1.0578x over previous
#include <cuda_runtime.h>
#include <cstdint>

#define SIZE_SETS 50000
#define NS 32
#define OUTP 64
#define MID 8
#define NROWS (SIZE_SETS * NS)
#define WPB 4                      // warps per block
#define BN_BLOCKS 592

// dynamic smem layout (floats): 8 staging buffers of 32*68, then weights, consts, bv
#define STAGE_F (32 * 68)
#define W_OFF   (8 * STAGE_F)          // 17408
#define C_OFF   (W_OFF + 1024)         // 18432
#define BV_OFF  (C_OFF + 32)           // 18464
#define SMEM_FLOATS (BV_OFF + 8)       // 18472
#define SMEM_BYTES  (SMEM_FLOATS * 4)  // 73888

// ---------------- device scratch (no allocation allowed) ----------------
__device__ __align__(128) float  g_acc[SIZE_SETS * 16]; // [s][0..7]=gsum, [8..15]=numer
__device__ float  g_bnp[BN_BLOCKS][5];                  // per-block moment partials
__device__ float  g_consts[32];                         // [0..3]=A, [4..5]=shift, [6..13]=C0, [14..21]=C1, [22..29]=D

// ---------------- helpers ----------------
__device__ __forceinline__ void ffma2(unsigned long long& d, unsigned long long a, unsigned long long b) {
    asm("fma.rn.f32x2 %0, %1, %2, %0;" : "+l"(d) : "l"(a), "l"(b));
}
__device__ __forceinline__ void fadd2(unsigned long long& d, unsigned long long a) {
    asm("add.rn.f32x2 %0, %1, %0;" : "+l"(d) : "l"(a));
}
__device__ __forceinline__ float2 unpk(unsigned long long v) {
    float2 r; asm("mov.b64 {%0, %1}, %2;" : "=f"(r.x), "=f"(r.y) : "l"(v)); return r;
}
__device__ __forceinline__ unsigned long long pk(float x, float y) {
    unsigned long long r; asm("mov.b64 %0, {%1, %2};" : "=l"(r) : "f"(x), "f"(y)); return r;
}
__device__ __forceinline__ void red4(float* p, float a, float b, float c, float d) {
    asm volatile("red.global.add.v4.f32 [%0], {%1, %2, %3, %4};"
                 :: "l"(p), "f"(a), "f"(b), "f"(c), "f"(d) : "memory");
}

// ---------------- kernel 1: zero g_acc + per-block raw moments of translation ----------------
__global__ void k_bn(const float* __restrict__ tr) {
    for (int k = blockIdx.x * blockDim.x + threadIdx.x; k < SIZE_SETS * 16;
         k += gridDim.x * blockDim.x) g_acc[k] = 0.f;

    float s0 = 0.f, s1 = 0.f, q00 = 0.f, q01 = 0.f, q11 = 0.f;
    const float2* t2 = (const float2*)tr;
    for (int i = blockIdx.x * blockDim.x + threadIdx.x; i < NROWS; i += gridDim.x * blockDim.x) {
        float2 t = t2[i];
        s0 += t.x; s1 += t.y;
        q00 += t.x * t.x; q01 += t.x * t.y; q11 += t.y * t.y;
    }
    #pragma unroll
    for (int o = 16; o; o >>= 1) {
        s0  += __shfl_down_sync(0xffffffffu, s0, o);
        s1  += __shfl_down_sync(0xffffffffu, s1, o);
        q00 += __shfl_down_sync(0xffffffffu, q00, o);
        q01 += __shfl_down_sync(0xffffffffu, q01, o);
        q11 += __shfl_down_sync(0xffffffffu, q11, o);
    }
    __shared__ float sh[5][8];
    int w = threadIdx.x >> 5, l = threadIdx.x & 31;
    if (l == 0) { sh[0][w] = s0; sh[1][w] = s1; sh[2][w] = q00; sh[3][w] = q01; sh[4][w] = q11; }
    __syncthreads();
    if (threadIdx.x < 5) {
        float t = 0.f;
        #pragma unroll
        for (int k = 0; k < 8; k++) t += sh[threadIdx.x][k];
        g_bnp[blockIdx.x][threadIdx.x] = t;
    }
}

// ---------------- kernel 2: reduce moments, fold BN + positional constants ----------------
__global__ void k_setup(const float* __restrict__ Wq, const float* __restrict__ bq,
                        const float* __restrict__ Wp1, const float* __restrict__ gamma,
                        const float* __restrict__ beta, const float* __restrict__ Wp2,
                        const float* __restrict__ bp2) {
    __shared__ double bn[5];
    int t = threadIdx.x;
    if (t < 5) {
        double acc = 0.0;
        for (int i = 0; i < BN_BLOCKS; i++) acc += (double)g_bnp[i][t];
        bn[t] = acc;
    }
    __syncthreads();
    if (t < 2) {
        double Nf = (double)NROWS;
        double w0 = (double)Wp1[t * 2 + 0], w1 = (double)Wp1[t * 2 + 1];
        double Tsum = w0 * bn[0] + w1 * bn[1];
        double Tsq  = w0 * w0 * bn[2] + 2.0 * w0 * w1 * bn[3] + w1 * w1 * bn[4];
        double mean = Tsum / Nf;
        double var  = Tsq / Nf - mean * mean;
        double scale = (double)gamma[t] / sqrt(var + 1e-5);
        double shift = (double)beta[t] - mean * scale;
        g_consts[t * 2 + 0] = (float)(w0 * scale);
        g_consts[t * 2 + 1] = (float)(w1 * scale);
        g_consts[4 + t]     = (float)shift;
    }
    if (t < 8) {
        float c0 = 0.f, c1 = 0.f, d = 0.f;
        for (int k = 0; k < OUTP; k++) {
            float wq = Wq[t * OUTP + k];
            c0 += Wp2[k * 2 + 0] * wq;
            c1 += Wp2[k * 2 + 1] * wq;
            d  += bp2[k] * wq;
        }
        g_consts[6 + t]  = c0;
        g_consts[14 + t] = c1;
        g_consts[22 + t] = d + bq[t];
    }
}

// ---------------- kernel 3: fused main — 4 warps/block, 2 sets/warp, no block syncs ----------------
__global__ void __launch_bounds__(128, 3)
k_main(const float* __restrict__ outputs, const float* __restrict__ translation,
       const int* __restrict__ indexes, const float* __restrict__ Wq,
       const float* __restrict__ Wv, const float* __restrict__ bv_,
       float* __restrict__ out) {
    extern __shared__ __align__(16) float dyn[];
    float* sh_w  = dyn + W_OFF;    // [0..511]=Wq, [512..1023]=Wv
    float* sh_c  = dyn + C_OFF;
    float* sh_bv = dyn + BV_OFF;

    int tid = threadIdx.x;
    for (int i = tid; i < 512; i += 128) { sh_w[i] = Wq[i]; sh_w[512 + i] = Wv[i]; }
    if (tid < 32) sh_c[tid] = g_consts[tid];
    if (tid < 8)  sh_bv[tid] = bv_[tid];
    __syncthreads();

    const float A00 = sh_c[0], A01 = sh_c[1], A10 = sh_c[2], A11 = sh_c[3];
    const float SH0 = sh_c[4], SH1 = sh_c[5];

    int warp = tid >> 5, lane = tid & 31;
    int c4 = lane & 15, rhalf = lane >> 4;
    float* myx0 = dyn + (warp * 2 + 0) * STAGE_F;
    float* myx1 = dyn + (warp * 2 + 1) * STAGE_F;

    const ulonglong2* wq  = (const ulonglong2*)&sh_w[0];
    const ulonglong2* wv  = (const ulonglong2*)&sh_w[512];
    const ulonglong2* xr0 = (const ulonglong2*)&myx0[lane * 68];
    const ulonglong2* xr1 = (const ulonglong2*)&myx1[lane * 68];

    const int stride = gridDim.x * WPB * 2;
    for (int s0 = (blockIdx.x * WPB + warp) * 2; s0 < SIZE_SETS; s0 += stride) {
        int s1 = s0 + 1;
        float2 t2v0 = ((const float2*)translation)[s0 * NS + lane];
        float2 t2v1 = ((const float2*)translation)[s1 * NS + lane];
        int idx0 = indexes[s0 * NS + lane];
        int idx1 = indexes[s1 * NS + lane];

        // --- stage set0 (16 coalesced LDG.128) + its feature sums ---
        unsigned long long f0lo = 0ull, f0hi = 0ull;
        {
            const float4* src = (const float4*)(outputs + (size_t)s0 * (NS * OUTP));
            #pragma unroll
            for (int t = 0; t < 16; t++) {
                float4 v = src[lane + 32 * t];
                fadd2(f0lo, pk(v.x, v.y)); fadd2(f0hi, pk(v.z, v.w));
                *(float4*)&myx0[(rhalf + 2 * t) * 68 + c4 * 4] = v;
            }
        }
        // --- stage set1 ---
        unsigned long long f1lo = 0ull, f1hi = 0ull;
        {
            const float4* src = (const float4*)(outputs + (size_t)s1 * (NS * OUTP));
            #pragma unroll
            for (int t = 0; t < 16; t++) {
                float4 v = src[lane + 32 * t];
                fadd2(f1lo, pk(v.x, v.y)); fadd2(f1hi, pk(v.z, v.w));
                *(float4*)&myx1[(rhalf + 2 * t) * 68 + c4 * 4] = v;
            }
        }
        fadd2(f0lo, __shfl_xor_sync(0xffffffffu, f0lo, 16));
        fadd2(f0hi, __shfl_xor_sync(0xffffffffu, f0hi, 16));
        fadd2(f1lo, __shfl_xor_sync(0xffffffffu, f1lo, 16));
        fadd2(f1hi, __shfl_xor_sync(0xffffffffu, f1hi, 16));
        {
            float2 alo = unpk(f0lo), ahi = unpk(f0hi);
            float2 blo = unpk(f1lo), bhi = unpk(f1hi);
            if (lane < 16)
                *(float4*)&out[(size_t)s0 * OUTP + lane * 4] = make_float4(alo.x, alo.y, ahi.x, ahi.y);
            else
                *(float4*)&out[(size_t)s1 * OUTP + (lane - 16) * 4] = make_float4(blo.x, blo.y, bhi.x, bhi.y);
        }
        __syncwarp();

        // --- q/v dots for both sets: weights broadcast once per pair ---
        unsigned long long q0[8], v0a[8], q1[8], v1a[8];
        #pragma unroll
        for (int j = 0; j < 8; j++) { q0[j] = v0a[j] = q1[j] = v1a[j] = 0ull; }

        #pragma unroll 2
        for (int k4 = 0; k4 < 16; k4++) {
            ulonglong2 x0 = xr0[k4];
            ulonglong2 x1 = xr1[k4];
            #pragma unroll
            for (int j = 0; j < 8; j++) {
                ulonglong2 a = wq[j * 16 + k4];
                ulonglong2 b = wv[j * 16 + k4];
                ffma2(q0[j], x0.x, a.x); ffma2(q0[j], x0.y, a.y);
                ffma2(q1[j], x1.x, a.x); ffma2(q1[j], x1.y, a.y);
                ffma2(v0a[j], x0.x, b.x); ffma2(v0a[j], x0.y, b.y);
                ffma2(v1a[j], x1.x, b.x); ffma2(v1a[j], x1.y, b.y);
            }
        }
        __syncwarp();   // all lanes done reading staging before next iteration

        // --- epilogue set 0 ---
        {
            float a0 = fmaxf(fmaf(A00, t2v0.x, fmaf(A01, t2v0.y, SH0)), 0.f);
            float a1 = fmaxf(fmaf(A10, t2v0.x, fmaf(A11, t2v0.y, SH1)), 0.f);
            float e8[8], ve8[8];
            #pragma unroll
            for (int j = 0; j < 8; j++) {
                float2 qq = unpk(q0[j]);
                float qs = qq.x + qq.y + fmaf(a0, sh_c[6 + j], fmaf(a1, sh_c[14 + j], sh_c[22 + j]));
                float2 vv = unpk(v0a[j]);
                float vs = vv.x + vv.y + sh_bv[j];
                float e = __expf(qs);                 // max-shift removed (q bounded)
                e8[j] = e; ve8[j] = vs * e;
            }
            float* dst = &g_acc[(size_t)idx0 * 16];
            red4(dst + 0,  e8[0],  e8[1],  e8[2],  e8[3]);
            red4(dst + 4,  e8[4],  e8[5],  e8[6],  e8[7]);
            red4(dst + 8,  ve8[0], ve8[1], ve8[2], ve8[3]);
            red4(dst + 12, ve8[4], ve8[5], ve8[6], ve8[7]);
        }
        // --- epilogue set 1 ---
        {
            float a0 = fmaxf(fmaf(A00, t2v1.x, fmaf(A01, t2v1.y, SH0)), 0.f);
            float a1 = fmaxf(fmaf(A10, t2v1.x, fmaf(A11, t2v1.y, SH1)), 0.f);
            float e8[8], ve8[8];
            #pragma unroll
            for (int j = 0; j < 8; j++) {
                float2 qq = unpk(q1[j]);
                float qs = qq.x + qq.y + fmaf(a0, sh_c[6 + j], fmaf(a1, sh_c[14 + j], sh_c[22 + j]));
                float2 vv = unpk(v1a[j]);
                float vs = vv.x + vv.y + sh_bv[j];
                float e = __expf(qs);
                e8[j] = e; ve8[j] = vs * e;
            }
            float* dst = &g_acc[(size_t)idx1 * 16];
            red4(dst + 0,  e8[0],  e8[1],  e8[2],  e8[3]);
            red4(dst + 4,  e8[4],  e8[5],  e8[6],  e8[7]);
            red4(dst + 8,  ve8[0], ve8[1], ve8[2], ve8[3]);
            red4(dst + 12, ve8[4], ve8[5], ve8[6], ve8[7]);
        }
    }
}

// ---------------- kernel 4: finalize out += tiled(numer/gsum), float4 ----------------
__global__ void k_fin(float* __restrict__ out) {
    int i = blockIdx.x * blockDim.x + threadIdx.x;      // float4 index
    if (i < SIZE_SETS * 16) {
        int s  = i >> 4;
        int q4 = i & 15;
        int jb = (q4 & 1) * 4;
        float4 g = *(const float4*)&g_acc[s * 16 + jb];
        float4 n = *(const float4*)&g_acc[s * 16 + 8 + jb];
        float4 o = *(float4*)&out[(size_t)i * 4];
        o.x += (g.x > 0.f) ? n.x / g.x : 0.f;
        o.y += (g.y > 0.f) ? n.y / g.y : 0.f;
        o.z += (g.z > 0.f) ? n.z / g.z : 0.f;
        o.w += (g.w > 0.f) ? n.w / g.w : 0.f;
        *(float4*)&out[(size_t)i * 4] = o;
    }
}

// ---------------- launch ----------------
extern "C" void kernel_launch(void* const* d_in, const int* in_sizes, int n_in,
                              void* d_out, int out_size) {
    const float* outputs     = (const float*)d_in[0];
    const float* translation = (const float*)d_in[1];
    const int*   indexes     = (const int*)d_in[2];
    const float* W_q   = (const float*)d_in[3];
    const float* b_q   = (const float*)d_in[4];
    const float* W_v   = (const float*)d_in[5];
    const float* b_v   = (const float*)d_in[6];
    const float* W_p1  = (const float*)d_in[7];
    const float* gamma = (const float*)d_in[8];
    const float* beta  = (const float*)d_in[9];
    const float* W_p2  = (const float*)d_in[10];
    const float* b_p2  = (const float*)d_in[11];
    float* out = (float*)d_out;

    static int smem_set = 0;
    if (!smem_set) {
        cudaFuncSetAttribute(k_main, cudaFuncAttributeMaxDynamicSharedMemorySize, SMEM_BYTES);
        smem_set = 1;
    }

    k_bn<<<BN_BLOCKS, 256>>>(translation);
    k_setup<<<1, 64>>>(W_q, b_q, W_p1, gamma, beta, W_p2, b_p2);
    k_main<<<444, 128, SMEM_BYTES>>>(outputs, translation, indexes, W_q, W_v, b_v, out);
    k_fin<<<(SIZE_SETS * 16 + 255) / 256, 256>>>(out);
}

// round 13
// speedup vs baseline: 1.4890x; 1.4076x over previous
#include <cuda_runtime.h>
#include <cstdint>

#define SIZE_SETS 50000
#define NS 32
#define OUTP 64
#define NROWS (SIZE_SETS * NS)
#define WPB 4
#define BN_BLOCKS 592

// ---------------- device scratch (no allocation allowed) ----------------
// g_acc layout per set: 4 quads [4*t + {e_{2t}, e_{2t+1}, ve_{2t}, ve_{2t+1}}], t=0..3
__device__ __align__(128) float g_acc[SIZE_SETS * 16];
__device__ float g_bnp[BN_BLOCKS][5];
__device__ float g_consts[32];   // [0..3]=A, [4..5]=shift, [6..13]=C0, [14..21]=C1, [22..29]=D

// ---------------- helpers ----------------
__device__ __forceinline__ void fadd2(unsigned long long& d, unsigned long long a) {
    asm("add.rn.f32x2 %0, %1, %0;" : "+l"(d) : "l"(a));
}
__device__ __forceinline__ float2 unpk(unsigned long long v) {
    float2 r; asm("mov.b64 {%0, %1}, %2;" : "=f"(r.x), "=f"(r.y) : "l"(v)); return r;
}
__device__ __forceinline__ unsigned long long pk(float x, float y) {
    unsigned long long r; asm("mov.b64 %0, {%1, %2};" : "=l"(r) : "f"(x), "f"(y)); return r;
}
__device__ __forceinline__ void red4(float* p, float a, float b, float c, float d) {
    asm volatile("red.global.add.v4.f32 [%0], {%1, %2, %3, %4};"
                 :: "l"(p), "f"(a), "f"(b), "f"(c), "f"(d) : "memory");
}
__device__ __forceinline__ uint32_t prmt(uint32_t a, uint32_t b, uint32_t s) {
    uint32_t d; asm("prmt.b32 %0, %1, %2, %3;" : "=r"(d) : "r"(a), "r"(b), "r"(s)); return d;
}
// pack {lo16=bf16(x0), hi16=bf16(x1)}  (cvt d,a,b: d.hi=cvt(a), d.lo=cvt(b))
__device__ __forceinline__ uint32_t cvtbf2(float x1, float x0) {
    uint32_t d; asm("cvt.rn.bf16x2.f32 %0, %1, %2;" : "=r"(d) : "f"(x1), "f"(x0)); return d;
}
// hi/lo split of an f32 pair into two bf16x2 regs (hi = truncation, exact in bf16)
__device__ __forceinline__ void split2(float x0, float x1, uint32_t& hi, uint32_t& lo) {
    uint32_t u0 = __float_as_uint(x0), u1 = __float_as_uint(x1);
    hi = prmt(u0, u1, 0x7632);                       // {bf16_trunc(x0), bf16_trunc(x1)}
    float l0 = x0 - __uint_as_float(u0 & 0xffff0000u);
    float l1 = x1 - __uint_as_float(u1 & 0xffff0000u);
    lo = cvtbf2(l1, l0);
}
__device__ __forceinline__ void mma16816(float* c, const uint32_t* a, const uint32_t* b) {
    asm("mma.sync.aligned.m16n8k16.row.col.f32.bf16.bf16.f32 "
        "{%0,%1,%2,%3}, {%4,%5,%6,%7}, {%8,%9}, {%0,%1,%2,%3};"
        : "+f"(c[0]), "+f"(c[1]), "+f"(c[2]), "+f"(c[3])
        : "r"(a[0]), "r"(a[1]), "r"(a[2]), "r"(a[3]), "r"(b[0]), "r"(b[1]));
}

// ---------------- kernel 1: zero g_acc + per-block raw moments of translation ----------------
__global__ void k_bn(const float* __restrict__ tr) {
    for (int k = blockIdx.x * blockDim.x + threadIdx.x; k < SIZE_SETS * 16;
         k += gridDim.x * blockDim.x) g_acc[k] = 0.f;

    float s0 = 0.f, s1 = 0.f, q00 = 0.f, q01 = 0.f, q11 = 0.f;
    const float2* t2 = (const float2*)tr;
    for (int i = blockIdx.x * blockDim.x + threadIdx.x; i < NROWS; i += gridDim.x * blockDim.x) {
        float2 t = t2[i];
        s0 += t.x; s1 += t.y;
        q00 += t.x * t.x; q01 += t.x * t.y; q11 += t.y * t.y;
    }
    #pragma unroll
    for (int o = 16; o; o >>= 1) {
        s0  += __shfl_down_sync(0xffffffffu, s0, o);
        s1  += __shfl_down_sync(0xffffffffu, s1, o);
        q00 += __shfl_down_sync(0xffffffffu, q00, o);
        q01 += __shfl_down_sync(0xffffffffu, q01, o);
        q11 += __shfl_down_sync(0xffffffffu, q11, o);
    }
    __shared__ float sh[5][8];
    int w = threadIdx.x >> 5, l = threadIdx.x & 31;
    if (l == 0) { sh[0][w] = s0; sh[1][w] = s1; sh[2][w] = q00; sh[3][w] = q01; sh[4][w] = q11; }
    __syncthreads();
    if (threadIdx.x < 5) {
        float t = 0.f;
        #pragma unroll
        for (int k = 0; k < 8; k++) t += sh[threadIdx.x][k];
        g_bnp[blockIdx.x][threadIdx.x] = t;
    }
}

// ---------------- kernel 2: reduce moments, fold BN + positional constants ----------------
__global__ void k_setup(const float* __restrict__ Wq, const float* __restrict__ bq,
                        const float* __restrict__ Wp1, const float* __restrict__ gamma,
                        const float* __restrict__ beta, const float* __restrict__ Wp2,
                        const float* __restrict__ bp2) {
    __shared__ double bn[5];
    int t = threadIdx.x;
    if (t < 5) {
        double acc = 0.0;
        for (int i = 0; i < BN_BLOCKS; i++) acc += (double)g_bnp[i][t];
        bn[t] = acc;
    }
    __syncthreads();
    if (t < 2) {
        double Nf = (double)NROWS;
        double w0 = (double)Wp1[t * 2 + 0], w1 = (double)Wp1[t * 2 + 1];
        double Tsum = w0 * bn[0] + w1 * bn[1];
        double Tsq  = w0 * w0 * bn[2] + 2.0 * w0 * w1 * bn[3] + w1 * w1 * bn[4];
        double mean = Tsum / Nf;
        double var  = Tsq / Nf - mean * mean;
        double scale = (double)gamma[t] / sqrt(var + 1e-5);
        double shift = (double)beta[t] - mean * scale;
        g_consts[t * 2 + 0] = (float)(w0 * scale);
        g_consts[t * 2 + 1] = (float)(w1 * scale);
        g_consts[4 + t]     = (float)shift;
    }
    if (t < 8) {
        float c0 = 0.f, c1 = 0.f, d = 0.f;
        for (int k = 0; k < OUTP; k++) {
            float wq = Wq[t * OUTP + k];
            c0 += Wp2[k * 2 + 0] * wq;
            c1 += Wp2[k * 2 + 1] * wq;
            d  += bp2[k] * wq;
        }
        g_consts[6 + t]  = c0;
        g_consts[14 + t] = c1;
        g_consts[22 + t] = d + bq[t];
    }
}

// ---------------- kernel 3: fused main — warp = set, tensor-core q/v GEMM ----------------
__global__ void __launch_bounds__(128, 3)
k_main(const float* __restrict__ outputs, const float* __restrict__ translation,
       const int* __restrict__ indexes, const float* __restrict__ Wq,
       const float* __restrict__ Wv, const float* __restrict__ bv_,
       float* __restrict__ out) {
    __shared__ __align__(16) float  sh_x[WPB][32 * 68];  // per-warp staging, stride 68
    __shared__ __align__(8)  float2 sh_a[WPB][32];
    __shared__ int sh_idx[WPB][32];

    int tid = threadIdx.x, warp = tid >> 5, lane = tid & 31;
    int g = lane >> 2, t4 = lane & 3;                    // mma group / thread-in-group
    int j0 = 2 * t4, j1 = 2 * t4 + 1;

    // BN/positional constants (L1-resident tiny loads)
    const float A00 = g_consts[0], A01 = g_consts[1], A10 = g_consts[2], A11 = g_consts[3];
    const float SH0 = g_consts[4], SH1 = g_consts[5];
    const float C0a = g_consts[6 + j0],  C0b = g_consts[6 + j1];
    const float C1a = g_consts[14 + j0], C1b = g_consts[14 + j1];
    const float Da  = g_consts[22 + j0], Db  = g_consts[22 + j1];
    const float bva = bv_[j0], bvb = bv_[j1];

    // --- load weight B-fragments into registers, hi/lo bf16 split (once) ---
    // B-frag reg r of ktile kt: rows k = kt*16 + 2*t4 + 8*r (+0,+1), col j = g
    uint32_t bqh[4][2], bql[4][2], bvh[4][2], bvl[4][2];
    #pragma unroll
    for (int kt = 0; kt < 4; kt++)
        #pragma unroll
        for (int r = 0; r < 2; r++) {
            int k = kt * 16 + 2 * t4 + 8 * r;
            split2(Wq[g * 64 + k], Wq[g * 64 + k + 1], bqh[kt][r], bql[kt][r]);
            split2(Wv[g * 64 + k], Wv[g * 64 + k + 1], bvh[kt][r], bvl[kt][r]);
        }

    const float* xbase = &sh_x[warp][0] + g * 68 + 2 * t4;  // A-frag anchor (row g, col 2t)
    int c4 = lane & 15, rh = lane >> 4;                     // staging loader mapping

    for (int s = blockIdx.x * WPB + warp; s < SIZE_SETS; s += gridDim.x * WPB) {
        // --- per-row metadata (lane = row) ---
        float2 tv = ((const float2*)translation)[s * NS + lane];
        sh_idx[warp][lane] = indexes[s * NS + lane];
        float pa0 = fmaxf(fmaf(A00, tv.x, fmaf(A01, tv.y, SH0)), 0.f);
        float pa1 = fmaxf(fmaf(A10, tv.x, fmaf(A11, tv.y, SH1)), 0.f);
        sh_a[warp][lane] = make_float2(pa0, pa1);

        // --- stage set (16 coalesced LDG.128) + fused feature column sums ---
        const float4* src = (const float4*)(outputs + (size_t)s * (NS * OUTP));
        unsigned long long flo = 0ull, fhi = 0ull;
        #pragma unroll
        for (int tt = 0; tt < 16; tt++) {
            float4 v = src[lane + 32 * tt];
            fadd2(flo, pk(v.x, v.y)); fadd2(fhi, pk(v.z, v.w));
            *(float4*)&sh_x[warp][(rh + 2 * tt) * 68 + c4 * 4] = v;
        }
        fadd2(flo, __shfl_xor_sync(0xffffffffu, flo, 16));
        fadd2(fhi, __shfl_xor_sync(0xffffffffu, fhi, 16));
        if (lane < 16) {
            float2 a = unpk(flo), b = unpk(fhi);
            *(float4*)&out[(size_t)s * OUTP + lane * 4] = make_float4(a.x, a.y, b.x, b.y);
        }
        __syncwarp();

        // --- tensor-core GEMM: out[32,16] = x[32,64] @ [Wq;Wv]^T, 3-pass bf16 split ---
        float cq[2][4], cv[2][4];
        #pragma unroll
        for (int mt = 0; mt < 2; mt++)
            #pragma unroll
            for (int i = 0; i < 4; i++) { cq[mt][i] = 0.f; cv[mt][i] = 0.f; }

        #pragma unroll
        for (int kt = 0; kt < 4; kt++) {
            #pragma unroll
            for (int mt = 0; mt < 2; mt++) {
                // A-frag reg rr: row g + 8*(rr&1) + 16*mt, cols 2t + 8*(rr>>1) + 16*kt (+0,+1)
                uint32_t ah[4], al[4];
                #pragma unroll
                for (int rr = 0; rr < 4; rr++) {
                    const float2 xv = *(const float2*)(xbase + ((rr & 1) * 8 + mt * 16) * 68
                                                             + (rr >> 1) * 8 + kt * 16);
                    split2(xv.x, xv.y, ah[rr], al[rr]);
                }
                mma16816(cq[mt], ah, bqh[kt]);
                mma16816(cq[mt], al, bqh[kt]);
                mma16816(cq[mt], ah, bql[kt]);
                mma16816(cv[mt], ah, bvh[kt]);
                mma16816(cv[mt], al, bvh[kt]);
                mma16816(cv[mt], ah, bvl[kt]);
            }
        }

        // --- epilogue: C-frag (rows g+8a+16mt, cols 2t,2t+1) -> exp -> red.v4 ---
        #pragma unroll
        for (int mt = 0; mt < 2; mt++)
            #pragma unroll
            for (int aa = 0; aa < 2; aa++) {
                int r = g + 8 * aa + 16 * mt;
                float2 arow = sh_a[warp][r];
                int idx = sh_idx[warp][r];
                float q0 = cq[mt][2 * aa + 0] + fmaf(arow.x, C0a, fmaf(arow.y, C1a, Da));
                float q1 = cq[mt][2 * aa + 1] + fmaf(arow.x, C0b, fmaf(arow.y, C1b, Db));
                float e0 = __expf(q0), e1 = __expf(q1);      // max-shift removed (q bounded)
                float ve0 = (cv[mt][2 * aa + 0] + bva) * e0;
                float ve1 = (cv[mt][2 * aa + 1] + bvb) * e1;
                red4(&g_acc[(size_t)idx * 16 + 4 * t4], e0, e1, ve0, ve1);
            }
        __syncwarp();
    }
}

// ---------------- kernel 4: finalize out += tiled(numer/gsum) ----------------
// g_acc quad layout: [s*16 + 4p + {e0,e1,ve0,ve1}], p = j>>1
__global__ void k_fin(float* __restrict__ out) {
    int i = blockIdx.x * blockDim.x + threadIdx.x;      // float4 index into out
    if (i < SIZE_SETS * 16) {
        int s  = i >> 4;
        int c4 = i & 15;
        const float4* acc4 = (const float4*)g_acc;
        float4 P0 = acc4[s * 4 + (c4 & 1) * 2 + 0];     // {e_j, e_j+1, ve_j, ve_j+1}
        float4 P1 = acc4[s * 4 + (c4 & 1) * 2 + 1];
        float4 o = *(float4*)&out[(size_t)i * 4];
        o.x += (P0.x > 0.f) ? P0.z / P0.x : 0.f;
        o.y += (P0.y > 0.f) ? P0.w / P0.y : 0.f;
        o.z += (P1.x > 0.f) ? P1.z / P1.x : 0.f;
        o.w += (P1.y > 0.f) ? P1.w / P1.y : 0.f;
        *(float4*)&out[(size_t)i * 4] = o;
    }
}

// ---------------- launch ----------------
extern "C" void kernel_launch(void* const* d_in, const int* in_sizes, int n_in,
                              void* d_out, int out_size) {
    const float* outputs     = (const float*)d_in[0];
    const float* translation = (const float*)d_in[1];
    const int*   indexes     = (const int*)d_in[2];
    const float* W_q   = (const float*)d_in[3];
    const float* b_q   = (const float*)d_in[4];
    const float* W_v   = (const float*)d_in[5];
    const float* b_v   = (const float*)d_in[6];
    const float* W_p1  = (const float*)d_in[7];
    const float* gamma = (const float*)d_in[8];
    const float* beta  = (const float*)d_in[9];
    const float* W_p2  = (const float*)d_in[10];
    const float* b_p2  = (const float*)d_in[11];
    float* out = (float*)d_out;

    k_bn<<<BN_BLOCKS, 256>>>(translation);
    k_setup<<<1, 64>>>(W_q, b_q, W_p1, gamma, beta, W_p2, b_p2);
    k_main<<<1184, 128>>>(outputs, translation, indexes, W_q, W_v, b_v, out);
    k_fin<<<(SIZE_SETS * 16 + 255) / 256, 256>>>(out);
}